// round 1
// baseline (speedup 1.0000x reference)
#include <cuda_runtime.h>

#define N_TOK   98
#define N_DIM   512
#define N_HEADS 16
#define HD      32
#define N_BATCH 512
#define N_WIN   64
#define M_ROWS  (N_BATCH * N_TOK)   /* 50176 */
#define SCALE   0.17677669529663687f /* 32^-0.5 */

#define RS 36          /* q/k/v smem row stride (pad 32 -> 36, float4-aligned) */
#define SRS 100        /* score smem row stride */

// ---- scratch (device globals: allocation-free rule) ----
__device__ float g_Q[(size_t)N_BATCH * N_HEADS * N_TOK * HD];
__device__ float g_K[(size_t)N_BATCH * N_HEADS * N_TOK * HD];
__device__ float g_V[(size_t)N_BATCH * N_HEADS * N_TOK * HD];
__device__ float g_Att[(size_t)M_ROWS * N_DIM];
__device__ float g_biasH[N_HEADS * N_TOK * N_TOK];

// ============================================================
// 1) Gather relative-position bias into per-head dense table
// ============================================================
__global__ void bias_pre_kernel(const float* __restrict__ bias_table,
                                const int* __restrict__ rel_index) {
    int idx = blockIdx.x * 256 + threadIdx.x;
    if (idx >= N_HEADS * N_TOK * N_TOK) return;
    int h  = idx / (N_TOK * N_TOK);
    int ij = idx % (N_TOK * N_TOK);
    g_biasH[idx] = bias_table[rel_index[ij] * N_HEADS + h];
}

// ============================================================
// 2) SGEMM-NT: C[m,n] = sum_k A[m,k]*B[n,k]  (A,B K-major)
//    128x128x16 tile, 256 threads, 8x8 per-thread microtile.
//    MODE 0: QKV epilogue (scatter to g_Q/g_K/g_V, scale q, +bias)
//    MODE 1: proj epilogue (A taken from g_Att, write Cout + bias)
// ============================================================
template <int MODE>
__global__ __launch_bounds__(256, 2) void sgemm_nt_kernel(
    const float* __restrict__ Ain, const float* __restrict__ B,
    const float* __restrict__ bias, float* __restrict__ Cout) {
    const int K = N_DIM;
    __shared__ float As[16][128];
    __shared__ float Bs[16][128];
    const float* A = (MODE == 1) ? g_Att : Ain;

    const int tid = threadIdx.x;
    const int tx = tid & 15, ty = tid >> 4;
    const int m0 = blockIdx.y * 128;
    const int n0 = blockIdx.x * 128;

    float acc[8][8];
#pragma unroll
    for (int r = 0; r < 8; r++)
#pragma unroll
        for (int c = 0; c < 8; c++) acc[r][c] = 0.f;

    for (int k0 = 0; k0 < K; k0 += 16) {
#pragma unroll
        for (int l = 0; l < 2; l++) {
            int id  = tid * 2 + l;        // 0..511 float4 slots (128 rows x 4)
            int row = id >> 2;
            int col = (id & 3) << 2;
            float4 a = *(const float4*)(A + (size_t)(m0 + row) * K + k0 + col);
            As[col + 0][row] = a.x; As[col + 1][row] = a.y;
            As[col + 2][row] = a.z; As[col + 3][row] = a.w;
            float4 b = *(const float4*)(B + (size_t)(n0 + row) * K + k0 + col);
            Bs[col + 0][row] = b.x; Bs[col + 1][row] = b.y;
            Bs[col + 2][row] = b.z; Bs[col + 3][row] = b.w;
        }
        __syncthreads();
#pragma unroll
        for (int kk = 0; kk < 16; kk++) {
            float ar[8], br[8];
            *(float4*)&ar[0] = *(float4*)&As[kk][ty * 8];
            *(float4*)&ar[4] = *(float4*)&As[kk][ty * 8 + 4];
            *(float4*)&br[0] = *(float4*)&Bs[kk][tx * 8];
            *(float4*)&br[4] = *(float4*)&Bs[kk][tx * 8 + 4];
#pragma unroll
            for (int r = 0; r < 8; r++)
#pragma unroll
                for (int c = 0; c < 8; c++)
                    acc[r][c] = fmaf(ar[r], br[c], acc[r][c]);
        }
        __syncthreads();
    }

    const int nbase = n0 + tx * 8;
    float bb[8];
#pragma unroll
    for (int i = 0; i < 8; i++) bb[i] = bias[nbase + i];

    if (MODE == 1) {
#pragma unroll
        for (int r = 0; r < 8; r++) {
            int m = m0 + ty * 8 + r;
            float4 v0 = make_float4(acc[r][0] + bb[0], acc[r][1] + bb[1],
                                    acc[r][2] + bb[2], acc[r][3] + bb[3]);
            float4 v1 = make_float4(acc[r][4] + bb[4], acc[r][5] + bb[5],
                                    acc[r][6] + bb[6], acc[r][7] + bb[7]);
            *(float4*)(Cout + (size_t)m * N_DIM + nbase)     = v0;
            *(float4*)(Cout + (size_t)m * N_DIM + nbase + 4) = v1;
        }
    } else {
        // channel c -> (which = c/512, head = (c%512)/32, d = c%32)
        int which = nbase >> 9;
        int h     = (nbase >> 5) & 15;
        int dbase = nbase & 31;   // 8-aligned within a 32-wide head
        float* dst = (which == 0) ? g_Q : (which == 1 ? g_K : g_V);
        float s = (which == 0) ? SCALE : 1.0f;
#pragma unroll
        for (int r = 0; r < 8; r++) {
            int m   = m0 + ty * 8 + r;
            int b   = m / N_TOK;
            int tok = m - b * N_TOK;
            size_t off = (((size_t)b * N_HEADS + h) * N_TOK + tok) * HD + dbase;
            float4 v0 = make_float4((acc[r][0] + bb[0]) * s, (acc[r][1] + bb[1]) * s,
                                    (acc[r][2] + bb[2]) * s, (acc[r][3] + bb[3]) * s);
            float4 v1 = make_float4((acc[r][4] + bb[4]) * s, (acc[r][5] + bb[5]) * s,
                                    (acc[r][6] + bb[6]) * s, (acc[r][7] + bb[7]) * s);
            *(float4*)(dst + off)     = v0;
            *(float4*)(dst + off + 4) = v1;
        }
    }
}

// ============================================================
// 3) Fused attention: one CTA per (b,h).
//    S = (Q*SCALE) K^T + bias + mask; softmax; O = P V
//    Q/K/V padded to 100 rows (rows 98,99 zero) -> no bounds in tiles.
// ============================================================
__global__ __launch_bounds__(256, 2) void attn_kernel(const float* __restrict__ mask) {
    extern __shared__ float sm[];
    float* qsm = sm;              // 100 x RS
    float* ksm = sm + 100 * RS;
    float* vsm = sm + 200 * RS;
    float* Ssm = sm + 300 * RS;   // 100 x SRS

    const int tid = threadIdx.x;
    const int h = blockIdx.x;
    const int b = blockIdx.y;

    const size_t bh = (size_t)b * N_HEADS + h;
    const float* Qg = g_Q + bh * N_TOK * HD;
    const float* Kg = g_K + bh * N_TOK * HD;
    const float* Vg = g_V + bh * N_TOK * HD;

    // load 98x32 tiles (784 float4 each)
    for (int id = tid; id < 784; id += 256) {
        int row = id >> 3;
        int col = (id & 7) << 2;
        *(float4*)&qsm[row * RS + col] = *(const float4*)(Qg + id * 4);
        *(float4*)&ksm[row * RS + col] = *(const float4*)(Kg + id * 4);
        *(float4*)&vsm[row * RS + col] = *(const float4*)(Vg + id * 4);
    }
    if (tid < 72) {  // zero rows 98,99 (72 = 2*RS)
        qsm[98 * RS + tid] = 0.f;
        ksm[98 * RS + tid] = 0.f;
        vsm[98 * RS + tid] = 0.f;
    }
    __syncthreads();

    // ---- S = Q K^T (+bias +mask): 25x25 tiles of 4x4 ----
    const float* maskW = mask + (size_t)(b & (N_WIN - 1)) * N_TOK * N_TOK;
    const float* biasH = g_biasH + (size_t)h * N_TOK * N_TOK;
    for (int t = tid; t < 625; t += 256) {
        int ti = t / 25, tj = t % 25;
        float acc[4][4] = {};
#pragma unroll
        for (int d4 = 0; d4 < 8; d4++) {
            float4 qa[4], kb[4];
#pragma unroll
            for (int r = 0; r < 4; r++) qa[r] = *(float4*)&qsm[(ti * 4 + r) * RS + d4 * 4];
#pragma unroll
            for (int c = 0; c < 4; c++) kb[c] = *(float4*)&ksm[(tj * 4 + c) * RS + d4 * 4];
#pragma unroll
            for (int r = 0; r < 4; r++)
#pragma unroll
                for (int c = 0; c < 4; c++)
                    acc[r][c] += qa[r].x * kb[c].x + qa[r].y * kb[c].y +
                                 qa[r].z * kb[c].z + qa[r].w * kb[c].w;
        }
#pragma unroll
        for (int r = 0; r < 4; r++) {
            int i = ti * 4 + r;
#pragma unroll
            for (int c = 0; c < 4; c++) {
                int j = tj * 4 + c;
                float v = acc[r][c];
                if (i < N_TOK && j < N_TOK)
                    v += biasH[i * N_TOK + j] + maskW[i * N_TOK + j];
                Ssm[i * SRS + j] = v;
            }
        }
    }
    __syncthreads();

    // ---- softmax: warp per row ----
    const int warp = tid >> 5, lane = tid & 31;
    for (int i = warp; i < N_TOK; i += 8) {
        float* row = Ssm + i * SRS;
        float mx = -1e30f;
        for (int j = lane; j < N_TOK; j += 32) mx = fmaxf(mx, row[j]);
#pragma unroll
        for (int o = 16; o > 0; o >>= 1) mx = fmaxf(mx, __shfl_xor_sync(0xffffffffu, mx, o));
        float s = 0.f;
        for (int j = lane; j < N_TOK; j += 32) {
            float e = __expf(row[j] - mx);
            row[j] = e;
            s += e;
        }
#pragma unroll
        for (int o = 16; o > 0; o >>= 1) s += __shfl_xor_sync(0xffffffffu, s, o);
        float inv = 1.0f / s;
        for (int j = lane; j < N_TOK; j += 32) row[j] *= inv;
    }
    __syncthreads();

    // ---- O = P V : 25 i-tiles x 8 d-tiles of 4x4 ----
    if (tid < 200) {
        int ti = tid >> 3, dt = tid & 7;
        float acc[4][4] = {};
#pragma unroll 2
        for (int j = 0; j < N_TOK; j++) {
            float4 vv = *(float4*)&vsm[j * RS + dt * 4];
#pragma unroll
            for (int r = 0; r < 4; r++) {
                float p = Ssm[(ti * 4 + r) * SRS + j];
                acc[r][0] += p * vv.x;
                acc[r][1] += p * vv.y;
                acc[r][2] += p * vv.z;
                acc[r][3] += p * vv.w;
            }
        }
#pragma unroll
        for (int r = 0; r < 4; r++) {
            int i = ti * 4 + r;
            if (i < N_TOK) {
                float* dst = g_Att + ((size_t)(b * N_TOK + i)) * N_DIM + h * HD + dt * 4;
                *(float4*)dst = make_float4(acc[r][0], acc[r][1], acc[r][2], acc[r][3]);
            }
        }
    }
}

// ============================================================
extern "C" void kernel_launch(void* const* d_in, const int* in_sizes, int n_in,
                              void* d_out, int out_size) {
    const float* x          = (const float*)d_in[0];
    const float* mask       = (const float*)d_in[1];
    const float* qkv_w      = (const float*)d_in[2];
    const float* qkv_b      = (const float*)d_in[3];
    const float* proj_w     = (const float*)d_in[4];
    const float* proj_b     = (const float*)d_in[5];
    const float* bias_table = (const float*)d_in[6];
    const int*   rel_index  = (const int*)d_in[7];
    float* out = (float*)d_out;

    // 1) bias gather
    bias_pre_kernel<<<(N_HEADS * N_TOK * N_TOK + 255) / 256, 256>>>(bias_table, rel_index);

    // 2) QKV projection (M=50176, N=1536, K=512) -> scattered into g_Q/g_K/g_V
    sgemm_nt_kernel<0><<<dim3(12, 392), 256>>>(x, qkv_w, qkv_b, nullptr);

    // 3) fused window attention (one CTA per (b,h))
    const int attn_smem = (300 * RS + 100 * SRS) * (int)sizeof(float);  // 83200 B
    cudaFuncSetAttribute(attn_kernel, cudaFuncAttributeMaxDynamicSharedMemorySize, attn_smem);
    attn_kernel<<<dim3(N_HEADS, N_BATCH), 256, attn_smem>>>(mask);

    // 4) output projection (M=50176, N=512, K=512) -> d_out
    sgemm_nt_kernel<1><<<dim3(4, 392), 256>>>(nullptr, proj_w, proj_b, out);
}

// round 2
// speedup vs baseline: 1.0893x; 1.0893x over previous
#include <cuda_runtime.h>
#include <cstdint>

#define N_TOK   98
#define N_DIM   512
#define N_HEADS 16
#define HD      32
#define N_BATCH 512
#define N_WIN   64
#define M_ROWS  (N_BATCH * N_TOK)   /* 50176 */
#define SCALE   0.17677669529663687f /* 32^-0.5 */

#define RS 36          /* q/k/v smem row stride */
#define SRS 100        /* score smem row stride */
#define KS_STRIDE 136  /* gemm smem row stride (bank-conflict-free frag loads) */

// ---- scratch (device globals: allocation-free rule) ----
__device__ float g_Q[(size_t)N_BATCH * N_HEADS * N_TOK * HD];
__device__ float g_K[(size_t)N_BATCH * N_HEADS * N_TOK * HD];
__device__ float g_V[(size_t)N_BATCH * N_HEADS * N_TOK * HD];
__device__ float g_Att[(size_t)M_ROWS * N_DIM];
__device__ float g_biasH[N_HEADS * N_TOK * N_TOK];

// ============================================================
// 1) Gather relative-position bias into per-head dense table
// ============================================================
__global__ void bias_pre_kernel(const float* __restrict__ bias_table,
                                const int* __restrict__ rel_index) {
    int idx = blockIdx.x * 256 + threadIdx.x;
    if (idx >= N_HEADS * N_TOK * N_TOK) return;
    int h  = idx / (N_TOK * N_TOK);
    int ij = idx % (N_TOK * N_TOK);
    g_biasH[idx] = bias_table[rel_index[ij] * N_HEADS + h];
}

// ============================================================
// helpers: tf32 split
// ============================================================
__device__ __forceinline__ uint32_t f2tf32(float f) {
    uint32_t r;
    asm("cvt.rna.tf32.f32 %0, %1;" : "=r"(r) : "f"(f));
    return r;
}
__device__ __forceinline__ void split_tf32(float f, uint32_t& hi, uint32_t& lo) {
    hi = f2tf32(f);
    float rem = f - __uint_as_float(hi);
    lo = f2tf32(rem);
}

#define MMA_TF32(c, a0, a1, a2, a3, b0, b1)                                  \
    asm volatile(                                                            \
        "mma.sync.aligned.m16n8k8.row.col.f32.tf32.tf32.f32 "                \
        "{%0,%1,%2,%3}, {%4,%5,%6,%7}, {%8,%9}, {%0,%1,%2,%3};"              \
        : "+f"(c[0]), "+f"(c[1]), "+f"(c[2]), "+f"(c[3])                     \
        : "r"(a0), "r"(a1), "r"(a2), "r"(a3), "r"(b0), "r"(b1))

// ============================================================
// 2) GEMM-NT on tensor cores, 3xTF32:
//    C[m,n] = sum_k A[m,k]*B[n,k]  (both K-major, K=512)
//    CTA tile 128x128x16, 8 warps (2x4), warp tile 64x32 (m16n8k8)
//    MODE 0: QKV epilogue (scatter to g_Q/g_K/g_V, scale q, +bias)
//    MODE 1: proj epilogue (A taken from g_Att, write Cout + bias)
// ============================================================
template <int MODE>
__global__ __launch_bounds__(256) void gemm_tc_kernel(
    const float* __restrict__ Ain, const float* __restrict__ B,
    const float* __restrict__ bias, float* __restrict__ Cout) {
    const int K = N_DIM;
    __shared__ uint32_t Ah[16 * KS_STRIDE];
    __shared__ uint32_t Al[16 * KS_STRIDE];
    __shared__ uint32_t Bh[16 * KS_STRIDE];
    __shared__ uint32_t Bl[16 * KS_STRIDE];

    const float* A = (MODE == 1) ? g_Att : Ain;

    const int tid  = threadIdx.x;
    const int warp = tid >> 5, lane = tid & 31;
    const int wm = warp >> 2, wn = warp & 3;      // 2 x 4 warp grid
    const int m0 = blockIdx.y * 128;
    const int n0 = blockIdx.x * 128;

    // global load coords: 2 float4 each from A and B
    const int row0 = (tid * 2) >> 2, col0 = ((tid * 2) & 3) << 2;
    const int row1 = (tid * 2 + 1) >> 2, col1 = ((tid * 2 + 1) & 3) << 2;

    float c[4][4][4];
#pragma unroll
    for (int i = 0; i < 4; i++)
#pragma unroll
        for (int j = 0; j < 4; j++)
#pragma unroll
            for (int r = 0; r < 4; r++) c[i][j][r] = 0.f;

    float4 pa0, pa1, pb0, pb1;
    pa0 = *(const float4*)(A + (size_t)(m0 + row0) * K + col0);
    pa1 = *(const float4*)(A + (size_t)(m0 + row1) * K + col1);
    pb0 = *(const float4*)(B + (size_t)(n0 + row0) * K + col0);
    pb1 = *(const float4*)(B + (size_t)(n0 + row1) * K + col1);

    const int mrow = wm * 64 + (lane >> 2);
    const int ncol = wn * 32 + (lane >> 2);
    const int kq   = lane & 3;

    for (int k0 = 0; k0 < K; k0 += 16) {
        // store prefetched tile (with hi/lo split)
        {
            uint32_t h, l;
            float v[4];
            v[0] = pa0.x; v[1] = pa0.y; v[2] = pa0.z; v[3] = pa0.w;
#pragma unroll
            for (int i = 0; i < 4; i++) {
                split_tf32(v[i], h, l);
                Ah[(col0 + i) * KS_STRIDE + row0] = h;
                Al[(col0 + i) * KS_STRIDE + row0] = l;
            }
            v[0] = pa1.x; v[1] = pa1.y; v[2] = pa1.z; v[3] = pa1.w;
#pragma unroll
            for (int i = 0; i < 4; i++) {
                split_tf32(v[i], h, l);
                Ah[(col1 + i) * KS_STRIDE + row1] = h;
                Al[(col1 + i) * KS_STRIDE + row1] = l;
            }
            v[0] = pb0.x; v[1] = pb0.y; v[2] = pb0.z; v[3] = pb0.w;
#pragma unroll
            for (int i = 0; i < 4; i++) {
                split_tf32(v[i], h, l);
                Bh[(col0 + i) * KS_STRIDE + row0] = h;
                Bl[(col0 + i) * KS_STRIDE + row0] = l;
            }
            v[0] = pb1.x; v[1] = pb1.y; v[2] = pb1.z; v[3] = pb1.w;
#pragma unroll
            for (int i = 0; i < 4; i++) {
                split_tf32(v[i], h, l);
                Bh[(col1 + i) * KS_STRIDE + row1] = h;
                Bl[(col1 + i) * KS_STRIDE + row1] = l;
            }
        }
        __syncthreads();

        // prefetch next tile (LDG overlaps MMA below)
        if (k0 + 16 < K) {
            pa0 = *(const float4*)(A + (size_t)(m0 + row0) * K + k0 + 16 + col0);
            pa1 = *(const float4*)(A + (size_t)(m0 + row1) * K + k0 + 16 + col1);
            pb0 = *(const float4*)(B + (size_t)(n0 + row0) * K + k0 + 16 + col0);
            pb1 = *(const float4*)(B + (size_t)(n0 + row1) * K + k0 + 16 + col1);
        }

#pragma unroll
        for (int ks = 0; ks < 16; ks += 8) {
            uint32_t ah[4][4], al[4][4], bh[4][2], bl[4][2];
            const int kb = (ks + kq) * KS_STRIDE;
            const int kb4 = (ks + kq + 4) * KS_STRIDE;
#pragma unroll
            for (int mt = 0; mt < 4; mt++) {
                int m = mrow + mt * 16;
                ah[mt][0] = Ah[kb + m];      ah[mt][1] = Ah[kb + m + 8];
                ah[mt][2] = Ah[kb4 + m];     ah[mt][3] = Ah[kb4 + m + 8];
                al[mt][0] = Al[kb + m];      al[mt][1] = Al[kb + m + 8];
                al[mt][2] = Al[kb4 + m];     al[mt][3] = Al[kb4 + m + 8];
            }
#pragma unroll
            for (int nt = 0; nt < 4; nt++) {
                int n = ncol + nt * 8;
                bh[nt][0] = Bh[kb + n];      bh[nt][1] = Bh[kb4 + n];
                bl[nt][0] = Bl[kb + n];      bl[nt][1] = Bl[kb4 + n];
            }
#pragma unroll
            for (int mt = 0; mt < 4; mt++)
#pragma unroll
                for (int nt = 0; nt < 4; nt++) {
                    MMA_TF32(c[mt][nt], ah[mt][0], ah[mt][1], ah[mt][2], ah[mt][3],
                             bh[nt][0], bh[nt][1]);
                    MMA_TF32(c[mt][nt], ah[mt][0], ah[mt][1], ah[mt][2], ah[mt][3],
                             bl[nt][0], bl[nt][1]);
                    MMA_TF32(c[mt][nt], al[mt][0], al[mt][1], al[mt][2], al[mt][3],
                             bh[nt][0], bh[nt][1]);
                }
        }
        __syncthreads();
    }

    // ---- epilogue ----
#pragma unroll
    for (int nt = 0; nt < 4; nt++) {
        const int n = n0 + wn * 32 + nt * 8 + (lane & 3) * 2;
        const float b0v = bias[n], b1v = bias[n + 1];
        if (MODE == 1) {
#pragma unroll
            for (int mt = 0; mt < 4; mt++) {
                int m = m0 + wm * 64 + mt * 16 + (lane >> 2);
                *(float2*)(Cout + (size_t)m * N_DIM + n) =
                    make_float2(c[mt][nt][0] + b0v, c[mt][nt][1] + b1v);
                *(float2*)(Cout + (size_t)(m + 8) * N_DIM + n) =
                    make_float2(c[mt][nt][2] + b0v, c[mt][nt][3] + b1v);
            }
        } else {
            const int which = n >> 9;
            const int h = (n >> 5) & 15;
            const int d = n & 31;
            float* dst = (which == 0) ? g_Q : (which == 1 ? g_K : g_V);
            const float s = (which == 0) ? SCALE : 1.0f;
#pragma unroll
            for (int mt = 0; mt < 4; mt++) {
                int m = m0 + wm * 64 + mt * 16 + (lane >> 2);
                int b = m / N_TOK, tok = m - b * N_TOK;
                size_t off = (((size_t)b * N_HEADS + h) * N_TOK + tok) * HD + d;
                *(float2*)(dst + off) =
                    make_float2((c[mt][nt][0] + b0v) * s, (c[mt][nt][1] + b1v) * s);
                b = (m + 8) / N_TOK; tok = (m + 8) - b * N_TOK;
                off = (((size_t)b * N_HEADS + h) * N_TOK + tok) * HD + d;
                *(float2*)(dst + off) =
                    make_float2((c[mt][nt][2] + b0v) * s, (c[mt][nt][3] + b1v) * s);
            }
        }
    }
}

// ============================================================
// 3) Fused attention: one CTA per (b,h).
// ============================================================
__global__ __launch_bounds__(256, 2) void attn_kernel(const float* __restrict__ mask) {
    extern __shared__ float sm[];
    float* qsm = sm;              // 100 x RS
    float* ksm = sm + 100 * RS;
    float* vsm = sm + 200 * RS;
    float* Ssm = sm + 300 * RS;   // 100 x SRS

    const int tid = threadIdx.x;
    const int h = blockIdx.x;
    const int b = blockIdx.y;

    const size_t bh = (size_t)b * N_HEADS + h;
    const float* Qg = g_Q + bh * N_TOK * HD;
    const float* Kg = g_K + bh * N_TOK * HD;
    const float* Vg = g_V + bh * N_TOK * HD;

    for (int id = tid; id < 784; id += 256) {
        int row = id >> 3;
        int col = (id & 7) << 2;
        *(float4*)&qsm[row * RS + col] = *(const float4*)(Qg + id * 4);
        *(float4*)&ksm[row * RS + col] = *(const float4*)(Kg + id * 4);
        *(float4*)&vsm[row * RS + col] = *(const float4*)(Vg + id * 4);
    }
    if (tid < 72) {
        qsm[98 * RS + tid] = 0.f;
        ksm[98 * RS + tid] = 0.f;
        vsm[98 * RS + tid] = 0.f;
    }
    __syncthreads();

    const float* maskW = mask + (size_t)(b & (N_WIN - 1)) * N_TOK * N_TOK;
    const float* biasH = g_biasH + (size_t)h * N_TOK * N_TOK;
    for (int t = tid; t < 625; t += 256) {
        int ti = t / 25, tj = t % 25;
        float acc[4][4] = {};
#pragma unroll
        for (int d4 = 0; d4 < 8; d4++) {
            float4 qa[4], kb[4];
#pragma unroll
            for (int r = 0; r < 4; r++) qa[r] = *(float4*)&qsm[(ti * 4 + r) * RS + d4 * 4];
#pragma unroll
            for (int cc = 0; cc < 4; cc++) kb[cc] = *(float4*)&ksm[(tj * 4 + cc) * RS + d4 * 4];
#pragma unroll
            for (int r = 0; r < 4; r++)
#pragma unroll
                for (int cc = 0; cc < 4; cc++)
                    acc[r][cc] += qa[r].x * kb[cc].x + qa[r].y * kb[cc].y +
                                  qa[r].z * kb[cc].z + qa[r].w * kb[cc].w;
        }
#pragma unroll
        for (int r = 0; r < 4; r++) {
            int i = ti * 4 + r;
#pragma unroll
            for (int cc = 0; cc < 4; cc++) {
                int j = tj * 4 + cc;
                float v = acc[r][cc];
                if (i < N_TOK && j < N_TOK)
                    v += biasH[i * N_TOK + j] + maskW[i * N_TOK + j];
                Ssm[i * SRS + j] = v;
            }
        }
    }
    __syncthreads();

    const int warp = tid >> 5, lane = tid & 31;
    for (int i = warp; i < N_TOK; i += 8) {
        float* row = Ssm + i * SRS;
        float mx = -1e30f;
        for (int j = lane; j < N_TOK; j += 32) mx = fmaxf(mx, row[j]);
#pragma unroll
        for (int o = 16; o > 0; o >>= 1) mx = fmaxf(mx, __shfl_xor_sync(0xffffffffu, mx, o));
        float s = 0.f;
        for (int j = lane; j < N_TOK; j += 32) {
            float e = __expf(row[j] - mx);
            row[j] = e;
            s += e;
        }
#pragma unroll
        for (int o = 16; o > 0; o >>= 1) s += __shfl_xor_sync(0xffffffffu, s, o);
        float inv = 1.0f / s;
        for (int j = lane; j < N_TOK; j += 32) row[j] *= inv;
    }
    __syncthreads();

    if (tid < 200) {
        int ti = tid >> 3, dt = tid & 7;
        float acc[4][4] = {};
#pragma unroll 2
        for (int j = 0; j < N_TOK; j++) {
            float4 vv = *(float4*)&vsm[j * RS + dt * 4];
#pragma unroll
            for (int r = 0; r < 4; r++) {
                float p = Ssm[(ti * 4 + r) * SRS + j];
                acc[r][0] += p * vv.x;
                acc[r][1] += p * vv.y;
                acc[r][2] += p * vv.z;
                acc[r][3] += p * vv.w;
            }
        }
#pragma unroll
        for (int r = 0; r < 4; r++) {
            int i = ti * 4 + r;
            if (i < N_TOK) {
                float* dst = g_Att + ((size_t)(b * N_TOK + i)) * N_DIM + h * HD + dt * 4;
                *(float4*)dst = make_float4(acc[r][0], acc[r][1], acc[r][2], acc[r][3]);
            }
        }
    }
}

// ============================================================
extern "C" void kernel_launch(void* const* d_in, const int* in_sizes, int n_in,
                              void* d_out, int out_size) {
    const float* x          = (const float*)d_in[0];
    const float* mask       = (const float*)d_in[1];
    const float* qkv_w      = (const float*)d_in[2];
    const float* qkv_b      = (const float*)d_in[3];
    const float* proj_w     = (const float*)d_in[4];
    const float* proj_b     = (const float*)d_in[5];
    const float* bias_table = (const float*)d_in[6];
    const int*   rel_index  = (const int*)d_in[7];
    float* out = (float*)d_out;

    bias_pre_kernel<<<(N_HEADS * N_TOK * N_TOK + 255) / 256, 256>>>(bias_table, rel_index);

    // QKV projection (M=50176, N=1536, K=512) -> scattered into g_Q/g_K/g_V
    gemm_tc_kernel<0><<<dim3(12, 392), 256>>>(x, qkv_w, qkv_b, nullptr);

    // fused window attention
    const int attn_smem = (300 * RS + 100 * SRS) * (int)sizeof(float);  // 83200 B
    cudaFuncSetAttribute(attn_kernel, cudaFuncAttributeMaxDynamicSharedMemorySize, attn_smem);
    attn_kernel<<<dim3(N_HEADS, N_BATCH), 256, attn_smem>>>(mask);

    // output projection (M=50176, N=512, K=512) -> d_out
    gemm_tc_kernel<1><<<dim3(4, 392), 256>>>(nullptr, proj_w, proj_b, out);
}